// round 17
// baseline (speedup 1.0000x reference)
#include <cuda_runtime.h>
#include <cstdint>

// Problem constants (fixed by the dataset)
#define BATCH   16
#define C_IN    64
#define HH      32
#define WW      32
#define C_OUT   128
#define PW      36            // padded row: 4 left + 32 data (cols 4..35)
#define SROWS   10            // rows staged per warp (8 outputs + 2 halo)
#define SPLANE  (SROWS*PW)    // 360 floats: one channel window per warp
#define SLAB    (2*SPLANE)    // 720: both channels, one warp
// Leaf reads span cols 3..36; col 36 wraps to the NEXT slab row's col 0,
// which is always a zeroed pad (rows are contiguous across planes/slabs);
// the very last row wraps into the explicit zeroed tail float4.
#define SMSZ    (4*SLAB + 4)  // 2884 floats

// 16B async copy global->shared (LDGSTS.128)
__device__ __forceinline__ void cp16(float* dst_smem, const float* src) {
    uint32_t d = (uint32_t)__cvta_generic_to_shared(dst_smem);
    asm volatile("cp.async.cg.shared.global [%0], [%1], 16;\n" :: "r"(d), "l"(src));
}

// gate(a,b) = c0 + ca*a + cb*b + cab*a*b, factored to 3 FMAs
__device__ __forceinline__ float gate3(const float4 k, float a, float b) {
    return fmaf(fmaf(k.w, b, k.y), a, fmaf(k.z, b, k.x));
}

// ---------------------------------------------------------------------------
// 128-thread block per (batch, oc); grid 2048, 16 blocks/SM -> one wave.
// PER-WARP pipelines: warp w owns output rows 8w..8w+7 and stages its own
// 10-row x 2-plane window with cp.async. The single __syncthreads publishes
// only coefficients/offsets/pad-zeros (no data wait); each warp then waits
// on ITS OWN copy group and computes — warps de-phase by memory return
// order, spreading LDS bursts. Hot loop: 8 LDS + 21 FMA + 1 STG per pixel.
// ---------------------------------------------------------------------------
__global__ void __launch_bounds__(128, 16)
tree_kernel(const float* __restrict__ x,
            const float* __restrict__ w,
            const int*   __restrict__ leaf_idx,
            float*       __restrict__ out)
{
    __shared__ __align__(16) float  sm[SMSZ];        // 11536 B
    __shared__ __align__(16) float  s_coef[16];
    __shared__ int s_off[8];

    const int blk  = blockIdx.x;         // 0..2047
    const int oc   = blk & (C_OUT - 1);
    const int b    = blk >> 7;
    const int tid  = threadIdx.x;        // 0..127
    const int warp = tid >> 5;
    const int lane = tid & 31;

    // --- channels (broadcast LDG; const-div -> mul-hi) ---------------------
    const int chA = __ldg(&leaf_idx[oc * 8 + 0]) / 9;
    const int chB = __ldg(&leaf_idx[oc * 8 + 4]) / 9;

    float* const slab = sm + warp * SLAB;

    // --- side pads: cols 0-3 of all 20 slab rows (contiguous) + tail -------
    {
        float4 z = make_float4(0.f, 0.f, 0.f, 0.f);
        if (lane < 20) *(float4*)(slab + lane * PW) = z;
        if (tid == 0)  *(float4*)(sm + 4 * SLAB) = z;    // tail pad
    }

    // --- per-warp staging: 2 planes x 10 rows x 8 chunks = 160 cp16 --------
    // (5 tasks per lane; rows outside the image are zero-filled via STS)
    {
        float4 z = make_float4(0.f, 0.f, 0.f, 0.f);
        const float* xb = x + ((size_t)b * C_IN) * (HH * WW);
        #pragma unroll
        for (int i = 0; i < 5; i++) {
            int t    = lane + i * 32;    // 0..159
            int p    = t >= 80;
            int j    = t - (p ? 80 : 0); // 0..79 = lr*8 + c4
            int lr   = j >> 3;
            int c4   = j & 7;
            int grow = (warp << 3) - 1 + lr;              // global input row
            float* dst = slab + p * SPLANE + lr * PW + 4 + c4 * 4;
            if ((unsigned)grow < 32u)
                cp16(dst, xb + ((p ? chB : chA) << 10) + grow * 32 + c4 * 4);
            else
                *(float4*)dst = z;       // halo row outside the image
        }
        asm volatile("cp.async.commit_group;\n");
    }

    // --- leaf offsets (slab-relative): threads 0..7 -------------------------
    if (tid < 8) {
        int idx = __ldg(&leaf_idx[oc * 8 + tid]);
        int ch  = idx / 9;
        int pos = idx - ch * 9;
        int ki  = pos / 3;
        int kj  = pos - ki * 3;
        s_off[tid] = (tid >> 2) * SPLANE + ki * PW + kj + 3;
    }

    // --- softmax -> 4 affine coefficients, threads 0..3 (gate = tid) -------
    // op order: 0, ab, a-ab, a, b-ab, b, s-2ab, s-ab, 1-(s-ab), 1-(s-2ab),
    //           1-b, 1-b+ab, 1-a, 1-a+ab, 1-ab, 1
    if (tid < 4) {
        const float T0[16]  = {0,0,0,0,0,0,0,0, 1, 1, 1, 1, 1, 1, 1, 1};
        const float TA[16]  = {0,0,1,1,0,0,1,1,-1,-1, 0, 0,-1,-1, 0, 0};
        const float TB[16]  = {0,0,0,0,1,1,1,1,-1,-1,-1,-1, 0, 0, 0, 0};
        const float TAB[16] = {0,1,-1,0,-1,0,-2,-1, 1, 2, 0, 1, 0, 1,-1, 0};

        const float* wp = w + (oc * 7 + tid) * 16;   // weights [C_out, 7, 16]

        float m = wp[0];
        #pragma unroll
        for (int i = 1; i < 16; i++) m = fmaxf(m, wp[i]);

        float e[16];
        float s = 0.f;
        #pragma unroll
        for (int i = 0; i < 16; i++) { e[i] = __expf(wp[i] - m); s += e[i]; }
        float inv = 1.f / s;

        float c0 = 0.f, ca = 0.f, cb = 0.f, cab = 0.f;
        #pragma unroll
        for (int i = 0; i < 16; i++) {
            c0  += e[i] * T0[i];
            ca  += e[i] * TA[i];
            cb  += e[i] * TB[i];
            cab += e[i] * TAB[i];
        }
        s_coef[tid * 4 + 0] = c0 * inv;
        s_coef[tid * 4 + 1] = ca * inv;
        s_coef[tid * 4 + 2] = cb * inv;
        s_coef[tid * 4 + 3] = cab * inv;
    }

    // --- publish s_off/s_coef/pads ONLY (does NOT wait for cp.async data) --
    __syncthreads();

    // Coefficients to registers (4x LDS.128)
    const float4* cf = (const float4*)s_coef;
    const float4 k0 = cf[0], k1 = cf[1], k2 = cf[2], k3 = cf[3];

    // 8 leaf base pointers within this warp's slab (lane = output column)
    const float* p0 = slab + s_off[0] + lane;
    const float* p1 = slab + s_off[1] + lane;
    const float* p2 = slab + s_off[2] + lane;
    const float* p3 = slab + s_off[3] + lane;
    const float* p4 = slab + s_off[4] + lane;
    const float* p5 = slab + s_off[5] + lane;
    const float* p6 = slab + s_off[6] + lane;
    const float* p7 = slab + s_off[7] + lane;

    // --- wait for THIS warp's staging only, then compute --------------------
    asm volatile("cp.async.wait_group 0;\n");
    __syncwarp();

    float* ob = out + (size_t)blk * (HH * WW) + (warp << 3) * WW + lane;

    #pragma unroll
    for (int oy = 0; oy < 8; oy++) {
        const int d = oy * PW;           // compile-time after unroll

        float l0 = p0[d], l1 = p1[d];
        float l2 = p2[d], l3 = p3[d];
        float l4 = p4[d], l5 = p5[d];
        float l6 = p6[d], l7 = p7[d];

        // level 0: weight rows 0,1,2,3
        float m0 = gate3(k0, l0, l1);
        float m1 = gate3(k1, l2, l3);
        float m2 = gate3(k2, l4, l5);
        float m3 = gate3(k3, l6, l7);
        // level 1: rows 1,2
        float n0 = gate3(k1, m0, m1);
        float n1 = gate3(k2, m2, m3);
        // level 2: row 3
        float r  = gate3(k3, n0, n1);

        ob[oy * WW] = r;                 // constant offset
    }
}

extern "C" void kernel_launch(void* const* d_in, const int* in_sizes, int n_in,
                              void* d_out, int out_size)
{
    const float* x   = (const float*)d_in[0];          // [16,64,32,32]
    const float* w   = (const float*)d_in[1];          // [128,7,16]
    const int*   idx = (const int*)d_in[2];            // [128,8]
    float*       out = (float*)d_out;                  // [16,128,32,32]

    tree_kernel<<<BATCH * C_OUT, 128>>>(x, w, idx, out);
}